// round 3
// baseline (speedup 1.0000x reference)
#include <cuda_runtime.h>
#include <math.h>

// ---------------- problem constants ----------------
#define NB    32
#define NCOL  160
#define NOUT  10
#define OFF_DIST 320
#define OFF_PROB 5440
#define OFF_LOSS 10560

#define NBLK  444                 // 148 SMs * 3 blocks
#define WB    484240              // weighted work per batch
#define WTOT  (484240LL*32)

// smem layout (words)
#define SXSTR 530                 // x row stride (512 data + 18 zero pad), 530%32=18 -> conflict-free
#define SXW   (8*SXSTR)           // 4240
#define SWW   (40*258)            // 10320 (max w region, set3)
#define SM_WORDS (SXW + SWW + 640)
#define SM_BYTES (SM_WORDS*4)     // 60800 B -> 3 blocks/SM

typedef unsigned long long ull;

// per-block partial results: [block][slot(2)][160]
__device__ unsigned g_pd[NBLK*320];
__device__ unsigned g_pq[NBLK*320];
__device__ int      g_pb[NBLK*2];

__device__ __forceinline__ unsigned fenc(float f){unsigned u=__float_as_uint(f);return (u&0x80000000u)?~u:(u|0x80000000u);}
__device__ __forceinline__ float fdec(unsigned e){unsigned u=(e&0x80000000u)?(e&0x7fffffffu):~e;return __uint_as_float(u);}

__device__ __forceinline__ ull addf2(ull a, ull b){
    ull r; asm("add.rn.f32x2 %0, %1, %2;" : "=l"(r) : "l"(a), "l"(b)); return r;
}
__device__ __forceinline__ float lo32(ull v){ return __uint_as_float((unsigned)(v & 0xffffffffull)); }
__device__ __forceinline__ float hi32(ull v){ return __uint_as_float((unsigned)(v >> 32)); }

template<int PAR>
__device__ __forceinline__ ull ldx(const float* p) {
    if (PAR == 0) {
        return *(const ull*)p;
    } else {
        float a = p[0], b = p[1];
        ull r; asm("mov.b64 %0, {%1, %2};" : "=l"(r) : "f"(a), "f"(b));
        return r;
    }
}

// ---------------- packed shapelet core (R2-validated structure) ----------------
// items indexed within one parity: idx in [i0,i1), tl = idx/40, nc = idx%40
template<int L, int M, int WW, int PAR, int SBASE>
__device__ __forceinline__ void proc(const float* __restrict__ sx, const float* __restrict__ sw,
                                     const float* __restrict__ pcm,
                                     unsigned* sden, unsigned* sq,
                                     int i0, int i1, int tid)
{
    constexpr int NP   = L/2;
    constexpr int REM  = NP % 8;
    constexpr int MAIN = NP - REM;
    constexpr bool ODDL = (L & 1);
    constexpr float INVL = 1.0f/(float)L;

    for (int idx = i0 + tid; idx < i1; idx += 256) {
        int tl = idx / 40;
        int nc = idx - tl*40;
        int c  = nc & 7;
        const float* xr = sx + c*SXSTR + 16*tl + PAR;
        const float* wr = sw + nc*WW;

        // prefetch pcm values (hidden behind the inner loop)
        float prv[8];
#pragma unroll
        for (int k = 0; k < 8; k++) {
            int mm = 16*tl + 2*k + PAR;
            prv[k] = __ldg(&pcm[c*M + (mm < M ? mm : M-1)]);
        }

        ull xq[8], acc[8];
#pragma unroll
        for (int k = 0; k < 8; k++) { xq[k] = ldx<PAR>(xr + 2*k); acc[k] = 0ull; }

        for (int st = 0; st < MAIN; st += 8) {
#pragma unroll
            for (int u = 0; u < 8; u++) {
                ull wp = *(const ull*)(wr + 2*(st+u));
#pragma unroll
                for (int k = 0; k < 8; k++) {
                    ull d = addf2(xq[(k+u)&7], wp);      // x + (-w)
                    d &= 0x7FFFFFFF7FFFFFFFull;          // packed abs
                    acc[k] = addf2(acc[k], d);
                }
                xq[u] = ldx<PAR>(xr + 2*(st+u) + 16);
            }
        }
#pragma unroll
        for (int u = 0; u < REM; u++) {
            ull wp = *(const ull*)(wr + 2*(MAIN+u));
#pragma unroll
            for (int k = 0; k < 8; k++) {
                ull d = addf2(xq[(k+u)&7], wp);
                d &= 0x7FFFFFFF7FFFFFFFull;
                acc[k] = addf2(acc[k], d);
            }
            xq[u&7] = ldx<PAR>(xr + 2*(MAIN+u) + 16);
        }

        float dmin = 3.4e38f, qmin = 3.4e38f;
#pragma unroll
        for (int k = 0; k < 8; k++) {
            int mm = 16*tl + 2*k + PAR;
            if (mm < M) {
                float ssum = lo32(acc[k]) + hi32(acc[k]);
                if (ODDL) ssum += fabsf(lo32(xq[(k+REM)&7]) + wr[L-1]);  // wr holds -w
                float d = ssum * INVL * prv[k];
                dmin = fminf(dmin, d);
                qmin = fminf(qmin, fabsf(d));
            }
        }
        atomicMin(&sden[SBASE + nc], fenc(dmin));
        atomicMin(&sq[SBASE + nc], __float_as_uint(qmin));
    }
}

// ---------------- main kernel: norm + shapelets, flat weighted partition ----------------
__global__ __launch_bounds__(256, 3)
void k_main(const float* __restrict__ x,
            const float* __restrict__ w0, const float* __restrict__ w1,
            const float* __restrict__ w2, const float* __restrict__ w3,
            const float* __restrict__ p0, const float* __restrict__ p1,
            const float* __restrict__ p2, const float* __restrict__ p3)
{
    extern __shared__ float sm[];
    float* sx = sm;                       // 8 * SXSTR
    float* sw = sm + SXW;                 // 40 * 258 max
    unsigned* sden = (unsigned*)(sm + SXW + SWW);   // [2][160]
    unsigned* sq   = sden + 320;                    // [2][160]

    int tid = threadIdx.x;
    int kb  = blockIdx.x;

    long long Bk  = (WTOT * kb) / NBLK;
    long long Bk1 = (WTOT * (kb+1)) / NBLK;
    int b_lo = (int)(Bk / WB);

    for (int i = tid; i < 640; i += 256) sden[i] = 0xFFFFFFFFu;  // covers sden+sq

    const float* wps[4] = {w0, w1, w2, w3};
    const float* pps[4] = {p0, p1, p2, p3};
    const int Cs[5]  = {0, 60320, 168480, 310160, 484240};
    const int wgt[4] = {26, 52, 77, 128};
    const int nss[4] = {2320, 2080, 1840, 1360};
    const int Lss[4] = {52, 103, 154, 256};
    const int WWs[4] = {66, 130, 162, 258};

    for (int slot = 0; slot < 2; slot++) {
        int b = b_lo + slot;
        if (b >= NB) break;
        long long bW  = (long long)b * WB;
        long long rlo = Bk  - bW; if (rlo < 0) rlo = 0;
        long long rhi = Bk1 - bW; if (rhi > WB) rhi = WB;
        if (rhi <= rlo) break;

        __syncthreads();   // protect sx/sden from previous slot's readers
        // --- normalize x rows for batch b into sx (warp w -> channel w) ---
        {
            int wp_ = tid >> 5, lane = tid & 31;
            const float* row = x + (b*8 + wp_)*512;
            float v[16]; float s = 0.f;
#pragma unroll
            for (int i = 0; i < 16; i++) { v[i] = row[lane + 32*i]; s += v[i]; }
#pragma unroll
            for (int o = 16; o; o >>= 1) s += __shfl_xor_sync(0xffffffffu, s, o);
            float mu = s * (1.f/512.f);
            float q = 0.f;
#pragma unroll
            for (int i = 0; i < 16; i++) { float d = v[i]-mu; q += d*d; }
#pragma unroll
            for (int o = 16; o; o >>= 1) q += __shfl_xor_sync(0xffffffffu, q, o);
            float sc = 1.f / (sqrtf(q * (1.f/511.f)) + 1e-8f);
            float* orow = sx + wp_*SXSTR;
#pragma unroll
            for (int i = 0; i < 16; i++) orow[lane + 32*i] = (v[i]-mu)*sc;
            if (lane < SXSTR - 512) orow[512 + lane] = 0.f;
        }

        for (int s = 0; s < 4; s++) {
            long long slo = rlo > Cs[s]   ? rlo : Cs[s];
            long long shi = rhi < Cs[s+1] ? rhi : Cs[s+1];
            if (slo >= shi) continue;
            int i0 = (int)((slo - Cs[s] + wgt[s] - 1) / wgt[s]);
            int i1 = (int)((shi - Cs[s] + wgt[s] - 1) / wgt[s]);
            if (i1 > nss[s]) i1 = nss[s];
            if (i0 >= i1) continue;

            __syncthreads();   // before overwriting sw
            int L = Lss[s], WW = WWs[s];
            const float* wp = wps[s];
            for (int i2 = tid; i2 < 40*L; i2 += 256) {
                int r = i2 / L, j = i2 - r*L;
                sw[r*WW + j] = -wp[i2];
            }
            __syncthreads();

            int half = nss[s] >> 1;
            int a0 = i0, a1 = i1 < half ? i1 : half;
            int c0 = (i0 > half ? i0 : half) - half, c1 = i1 - half;
            unsigned* sd = sden + slot*160;
            unsigned* sqs = sq + slot*160;
            switch (s) {
                case 0:
                    if (a0 < a1) proc< 52,461, 66,0,  0>(sx, sw, pps[0], sd, sqs, a0, a1, tid);
                    if (c0 < c1) proc< 52,461, 66,1,  0>(sx, sw, pps[0], sd, sqs, c0, c1, tid);
                    break;
                case 1:
                    if (a0 < a1) proc<103,410,130,0, 40>(sx, sw, pps[1], sd, sqs, a0, a1, tid);
                    if (c0 < c1) proc<103,410,130,1, 40>(sx, sw, pps[1], sd, sqs, c0, c1, tid);
                    break;
                case 2:
                    if (a0 < a1) proc<154,359,162,0, 80>(sx, sw, pps[2], sd, sqs, a0, a1, tid);
                    if (c0 < c1) proc<154,359,162,1, 80>(sx, sw, pps[2], sd, sqs, c0, c1, tid);
                    break;
                default:
                    if (a0 < a1) proc<256,257,258,0,120>(sx, sw, pps[3], sd, sqs, a0, a1, tid);
                    if (c0 < c1) proc<256,257,258,1,120>(sx, sw, pps[3], sd, sqs, c0, c1, tid);
                    break;
            }
        }
    }
    __syncthreads();
    for (int i = tid; i < 320; i += 256) {
        g_pd[kb*320 + i] = sden[i];
        g_pq[kb*320 + i] = sq[i];
    }
    if (tid == 0) { g_pb[kb*2 + 0] = b_lo; g_pb[kb*2 + 1] = b_lo + 1; }
}

// ---------------- final: reduce partials + decode + matmul + losses ----------------
__global__ void k_final(float* __restrict__ out, const float* __restrict__ Wout,
                        const float* __restrict__ w0, const float* __restrict__ w1,
                        const float* __restrict__ w2, const float* __restrict__ w3)
{
    int b = blockIdx.x, tid = threadIdx.x;
    if (b < NB) {
        __shared__ float sprob[NCOL];
        if (tid < NCOL) {
            unsigned de = 0xFFFFFFFFu, qe = 0xFFFFFFFFu;
            int klo = (NBLK*(b-1))/NB - 1; if (klo < 0) klo = 0;
            int khi = (NBLK*(b+1))/NB + 1; if (khi > NBLK-1) khi = NBLK-1;
            for (int kk = klo; kk <= khi; kk++) {
#pragma unroll
                for (int sl = 0; sl < 2; sl++) {
                    if (g_pb[kk*2 + sl] == b) {
                        unsigned dv = g_pd[kk*320 + sl*160 + tid];
                        unsigned qv = g_pq[kk*320 + sl*160 + tid];
                        de = de < dv ? de : dv;
                        qe = qe < qv ? qe : qv;
                    }
                }
            }
            float qv = __uint_as_float(qe);
            float p = expf(-qv*qv);
            out[OFF_DIST + b*NCOL + tid] = fdec(de);
            out[OFF_PROB + b*NCOL + tid] = p;
            sprob[tid] = p;
        }
        __syncthreads();
        if (tid < NOUT) {
            const float* wr = Wout + tid*NCOL;
            float acc = 0.f;
#pragma unroll 8
            for (int j = 0; j < NCOL; j++) acc += sprob[j]*wr[j];
            out[b*NOUT + tid] = acc;
        }
    } else {
        // losses
        float reg = 0.f;
        for (int i = tid; i < NOUT*NCOL; i += 256) reg += fabsf(Wout[i]);
        const int Ls[4] = {52, 103, 154, 256};
        const float* wps[4] = {w0, w1, w2, w3};
        float div = 0.f;
        for (int t = tid; t < 800; t += 256) {
            int s = t / 200; int r = t % 200;
            int c = r / 25; int ij = r % 25; int i = ij / 5, j = ij % 5;
            if (i == j) continue;
            int l = Ls[s];
            const float* wa = wps[s] + (i*8 + c)*l;
            const float* wb = wps[s] + (j*8 + c)*l;
            float ss = 0.f;
            for (int kk = 0; kk < l; kk++) { float d = wa[kk]-wb[kk]+1e-6f; ss += d*d; }
            div += expf(-sqrtf(ss)) * (1.f/200.f);
        }
        __shared__ float r1[256], r2[256];
        r1[tid] = reg; r2[tid] = div;
        __syncthreads();
        for (int off = 128; off; off >>= 1) {
            if (tid < off) { r1[tid] += r1[tid+off]; r2[tid] += r2[tid+off]; }
            __syncthreads();
        }
        if (tid == 0) out[OFF_LOSS] = 0.1f*(r1[0]/1600.f) + 0.1f*r2[0];
    }
}

// ---------------- launch ----------------
extern "C" void kernel_launch(void* const* d_in, const int* in_sizes, int n_in,
                              void* d_out, int out_size) {
    const float* x = nullptr;
    const float* w[4] = {nullptr,nullptr,nullptr,nullptr};
    const float* pcm[4] = {nullptr,nullptr,nullptr,nullptr};
    const float* Wout = nullptr;
    for (int i = 0; i < n_in; i++) {
        switch (in_sizes[i]) {
            case 131072: x = (const float*)d_in[i]; break;
            case 2080:  w[0] = (const float*)d_in[i]; break;
            case 4120:  w[1] = (const float*)d_in[i]; break;
            case 6160:  w[2] = (const float*)d_in[i]; break;
            case 10240: w[3] = (const float*)d_in[i]; break;
            case 3688:  pcm[0] = (const float*)d_in[i]; break;
            case 3280:  pcm[1] = (const float*)d_in[i]; break;
            case 2872:  pcm[2] = (const float*)d_in[i]; break;
            case 2056:  pcm[3] = (const float*)d_in[i]; break;
            case 1600:  Wout = (const float*)d_in[i]; break;
            default: break;
        }
    }
    float* out = (float*)d_out;

    cudaFuncSetAttribute(k_main, cudaFuncAttributeMaxDynamicSharedMemorySize, SM_BYTES);

    k_main<<<NBLK, 256, SM_BYTES>>>(x, w[0], w[1], w[2], w[3],
                                    pcm[0], pcm[1], pcm[2], pcm[3]);
    k_final<<<NB + 1, 256>>>(out, Wout, w[0], w[1], w[2], w[3]);
    (void)out_size;
}

// round 4
// speedup vs baseline: 1.3032x; 1.3032x over previous
#include <cuda_runtime.h>
#include <math.h>

// ---------------- problem constants ----------------
#define NB    32
#define NCOL  160
#define NOUT  10
#define OFF_DIST 320
#define OFF_PROB 5440
#define OFF_LOSS 10560

#define SLOTS 13
#define NBLK  (NB*SLOTS)          // 416 blocks = one wave at 3/SM

// smem layout (words)
#define SXSTR 530                 // 512 data + 18 zero pad; 530%32=18 -> conflict-free
#define SXW   (8*SXSTR)           // 4240
#define SWWMAX 258
#define SM_WORDS (SXW + 40*SWWMAX + 80)
#define SM_BYTES (SM_WORDS*4)     // 58560 B -> 3 blocks/SM

typedef unsigned long long ull;

// global result accumulators; inverted encoding so init/reset value is 0.
__device__ unsigned g_d[NB*NCOL] = {};
__device__ unsigned g_q[NB*NCOL] = {};

__device__ __forceinline__ unsigned fenc(float f){unsigned u=__float_as_uint(f);return (u&0x80000000u)?~u:(u|0x80000000u);}
__device__ __forceinline__ float fdec(unsigned e){unsigned u=(e&0x80000000u)?(e&0x7fffffffu):~e;return __uint_as_float(u);}
// inverted: larger ienc  <=>  smaller float. max(ienc) = min(f). ienc > 0 for any finite f.
__device__ __forceinline__ unsigned ienc(float f){ return ~fenc(f); }
__device__ __forceinline__ float idec(unsigned e){ return fdec(~e); }

__device__ __forceinline__ ull addf2(ull a, ull b){
    ull r; asm("add.rn.f32x2 %0, %1, %2;" : "=l"(r) : "l"(a), "l"(b)); return r;
}
__device__ __forceinline__ float lo32(ull v){ return __uint_as_float((unsigned)(v & 0xffffffffull)); }
__device__ __forceinline__ float hi32(ull v){ return __uint_as_float((unsigned)(v >> 32)); }

template<int PAR>
__device__ __forceinline__ ull ldx(const float* p) {
    if (PAR == 0) {
        return *(const ull*)p;
    } else {
        float a = p[0], b = p[1];
        ull r; asm("mov.b64 %0, {%1, %2};" : "=l"(r) : "f"(a), "f"(b));
        return r;
    }
}

// ---------------- packed shapelet core (R2/R3-validated) ----------------
template<int L, int M, int WW, int PAR>
__device__ __forceinline__ void proc(const float* __restrict__ sx, const float* __restrict__ sw,
                                     const float* __restrict__ pcm,
                                     unsigned* sden, unsigned* sq,
                                     int i0, int i1, int tid)
{
    constexpr int NP   = L/2;
    constexpr int REM  = NP % 8;
    constexpr int MAIN = NP - REM;
    constexpr bool ODDL = (L & 1);
    constexpr float INVL = 1.0f/(float)L;

    for (int idx = i0 + tid; idx < i1; idx += 256) {
        int tl = idx / 40;
        int nc = idx - tl*40;
        int c  = nc & 7;
        const float* xr = sx + c*SXSTR + 16*tl + PAR;
        const float* wr = sw + nc*WW;

        float prv[8];
#pragma unroll
        for (int k = 0; k < 8; k++) {
            int mm = 16*tl + 2*k + PAR;
            prv[k] = __ldg(&pcm[c*M + (mm < M ? mm : M-1)]);
        }

        ull xq[8], acc[8];
#pragma unroll
        for (int k = 0; k < 8; k++) { xq[k] = ldx<PAR>(xr + 2*k); acc[k] = 0ull; }

        for (int st = 0; st < MAIN; st += 8) {
#pragma unroll
            for (int u = 0; u < 8; u++) {
                ull wp = *(const ull*)(wr + 2*(st+u));
#pragma unroll
                for (int k = 0; k < 8; k++) {
                    ull d = addf2(xq[(k+u)&7], wp);      // x + (-w)
                    d &= 0x7FFFFFFF7FFFFFFFull;          // packed abs
                    acc[k] = addf2(acc[k], d);
                }
                xq[u] = ldx<PAR>(xr + 2*(st+u) + 16);
            }
        }
#pragma unroll
        for (int u = 0; u < REM; u++) {
            ull wp = *(const ull*)(wr + 2*(MAIN+u));
#pragma unroll
            for (int k = 0; k < 8; k++) {
                ull d = addf2(xq[(k+u)&7], wp);
                d &= 0x7FFFFFFF7FFFFFFFull;
                acc[k] = addf2(acc[k], d);
            }
            xq[u&7] = ldx<PAR>(xr + 2*(MAIN+u) + 16);
        }

        float dmin = 3.4e38f, qmin = 3.4e38f;
#pragma unroll
        for (int k = 0; k < 8; k++) {
            int mm = 16*tl + 2*k + PAR;
            if (mm < M) {
                float ssum = lo32(acc[k]) + hi32(acc[k]);
                if (ODDL) ssum += fabsf(lo32(xq[(k+REM)&7]) + wr[L-1]);  // wr holds -w
                float d = ssum * INVL * prv[k];
                dmin = fminf(dmin, d);
                qmin = fminf(qmin, fabsf(d));
            }
        }
        atomicMax(&sden[nc], ienc(dmin));
        atomicMax(&sq[nc],   ienc(qmin));
    }
}

// ---------------- main kernel: fused norm + shapelets ----------------
__global__ __launch_bounds__(256, 3)
void k_main(const float* __restrict__ x,
            const float* __restrict__ w0, const float* __restrict__ w1,
            const float* __restrict__ w2, const float* __restrict__ w3,
            const float* __restrict__ p0, const float* __restrict__ p1,
            const float* __restrict__ p2, const float* __restrict__ p3)
{
    extern __shared__ float sm[];
    float* sx = sm;                       // 8 * SXSTR
    float* sw = sm + SXW;                 // 40 * WW
    unsigned* sden = (unsigned*)(sm + SXW + 40*SWWMAX);   // [40]
    unsigned* sq   = sden + 40;                           // [40]

    const signed char SLOT_SET[SLOTS] = {0,0, 1,1,1, 2,2,2,2, 3,3,3,3};
    const int CHb[4] = {0, 2, 5, 9};
    const int CHn[4] = {2, 3, 4, 4};
    const int nss[4] = {2320, 2080, 1840, 1360};  // items, both parities
    const int Lss[4] = {52, 103, 154, 256};
    const int WWs[4] = {66, 130, 162, 258};

    int tid = threadIdx.x;
    int bx = blockIdx.x;
    int b = bx / SLOTS, slot = bx - b*SLOTS;
    int s = SLOT_SET[slot];
    int q = slot - CHb[s];
    int i0 = (nss[s]*q)/CHn[s], i1 = (nss[s]*(q+1))/CHn[s];
    int L = Lss[s], WW = WWs[s];
    const float* wp = (s==0)?w0:(s==1)?w1:(s==2)?w2:w3;
    const float* pp = (s==0)?p0:(s==1)?p1:(s==2)?p2:p3;

    if (tid < 80) sden[tid] = 0u;   // covers sden + sq

    // --- normalize x rows for batch b into sx (warp w -> channel w) ---
    {
        int wp_ = tid >> 5, lane = tid & 31;
        const float* row = x + (b*8 + wp_)*512;
        float v[16]; float sv = 0.f;
#pragma unroll
        for (int i = 0; i < 16; i++) { v[i] = row[lane + 32*i]; sv += v[i]; }
#pragma unroll
        for (int o = 16; o; o >>= 1) sv += __shfl_xor_sync(0xffffffffu, sv, o);
        float mu = sv * (1.f/512.f);
        float qq = 0.f;
#pragma unroll
        for (int i = 0; i < 16; i++) { float d = v[i]-mu; qq += d*d; }
#pragma unroll
        for (int o = 16; o; o >>= 1) qq += __shfl_xor_sync(0xffffffffu, qq, o);
        float sc = 1.f / (sqrtf(qq * (1.f/511.f)) + 1e-8f);
        float* orow = sx + wp_*SXSTR;
#pragma unroll
        for (int i = 0; i < 16; i++) orow[lane + 32*i] = (v[i]-mu)*sc;
        if (lane < SXSTR - 512) orow[512 + lane] = 0.f;
    }

    // --- stage negated weights for this set ---
    for (int i2 = tid; i2 < 40*L; i2 += 256) {
        int r = i2 / L, j = i2 - r*L;
        sw[r*WW + j] = -wp[i2];
    }
    __syncthreads();

    int half = nss[s] >> 1;
    int a0 = i0, a1 = i1 < half ? i1 : half;
    int c0 = (i0 > half ? i0 : half) - half, c1 = i1 - half;
    switch (s) {
        case 0:
            if (a0 < a1) proc< 52,461, 66,0>(sx, sw, pp, sden, sq, a0, a1, tid);
            if (c0 < c1) proc< 52,461, 66,1>(sx, sw, pp, sden, sq, c0, c1, tid);
            break;
        case 1:
            if (a0 < a1) proc<103,410,130,0>(sx, sw, pp, sden, sq, a0, a1, tid);
            if (c0 < c1) proc<103,410,130,1>(sx, sw, pp, sden, sq, c0, c1, tid);
            break;
        case 2:
            if (a0 < a1) proc<154,359,162,0>(sx, sw, pp, sden, sq, a0, a1, tid);
            if (c0 < c1) proc<154,359,162,1>(sx, sw, pp, sden, sq, c0, c1, tid);
            break;
        default:
            if (a0 < a1) proc<256,257,258,0>(sx, sw, pp, sden, sq, a0, a1, tid);
            if (c0 < c1) proc<256,257,258,1>(sx, sw, pp, sden, sq, c0, c1, tid);
            break;
    }
    __syncthreads();
    if (tid < 40) {
        int idx = b*NCOL + s*40 + tid;
        atomicMax(&g_d[idx], sden[tid]);
        atomicMax(&g_q[idx], sq[tid]);
    }
}

// ---------------- final: decode + reset + matmul + losses ----------------
__global__ void k_final(float* __restrict__ out, const float* __restrict__ Wout,
                        const float* __restrict__ w0, const float* __restrict__ w1,
                        const float* __restrict__ w2, const float* __restrict__ w3)
{
    __shared__ float shm[2304];
    int b = blockIdx.x, tid = threadIdx.x;   // 512 threads

    if (b < NB) {
        float* sprob = shm;                  // [160]
        if (tid < NCOL) {
            int idx = b*NCOL + tid;
            unsigned de = g_d[idx], qe = g_q[idx];
            g_d[idx] = 0u; g_q[idx] = 0u;    // reset for next replay
            float qv = idec(qe);
            float p = expf(-qv*qv);
            out[OFF_DIST + idx] = idec(de);
            out[OFF_PROB + idx] = p;
            sprob[tid] = p;
        }
        __syncthreads();
        if (tid < NOUT) {
            const float* wr = Wout + tid*NCOL;
            float acc = 0.f;
#pragma unroll 8
            for (int j = 0; j < NCOL; j++) acc += sprob[j]*wr[j];
            out[b*NOUT + tid] = acc;
        }
    } else {
        // ---- losses ----
        float* sf   = shm;            // [640] forward partial sums
        float* sr   = shm + 640;      // [640] reverse partial sums
        float* sval = shm + 1280;     // [512] diversity per-pair values
        float* sreg = shm + 1792;     // [512] reg partials

        const int Ls[4] = {52, 103, 154, 256};
        const float* wps[4] = {w0, w1, w2, w3};
        const signed char I1[10] = {0,0,0,0,1,1,1,2,2,3};
        const signed char J1[10] = {1,2,3,4,2,3,4,3,4,4};

        // reg partial
        float reg = 0.f;
        for (int i = tid; i < NOUT*NCOL; i += 512) reg += fabsf(Wout[i]);
        sreg[tid] = reg;

        // diversity partials: unit = pair*2 + half; pair = (s,c, i<j)
        for (int u = tid; u < 640; u += 512) {
            int p = u >> 1, h = u & 1;
            int s = p / 80; int r = p - s*80;
            int c = r / 10; int pr = r - c*10;
            int i = I1[pr], j = J1[pr];
            int L = Ls[s];
            const float* wa = wps[s] + (i*8 + c)*L;
            const float* wb = wps[s] + (j*8 + c)*L;
            int k0 = h ? (L >> 1) : 0;
            int k1 = h ? L : (L >> 1);
            float af = 0.f, ar = 0.f;
#pragma unroll 4
            for (int k = k0; k < k1; k++) {
                float t = wa[k] - wb[k];
                float df = t + 1e-6f, dr = 1e-6f - t;
                af += df*df; ar += dr*dr;
            }
            sf[u] = af; sr[u] = ar;
        }
        __syncthreads();

        // finalize pairs (fixed order)
        float val = 0.f;
        if (tid < 320) {
            float ssf = sf[2*tid] + sf[2*tid + 1];
            float ssr = sr[2*tid] + sr[2*tid + 1];
            val = (expf(-sqrtf(ssf)) + expf(-sqrtf(ssr))) * (1.f/200.f);
        }
        sval[tid] = val;
        __syncthreads();
        for (int off = 256; off; off >>= 1) {
            if (tid < off) { sval[tid] += sval[tid+off]; sreg[tid] += sreg[tid+off]; }
            __syncthreads();
        }
        if (tid == 0) out[OFF_LOSS] = 0.1f*(sreg[0]/1600.f) + 0.1f*sval[0];
    }
}

// ---------------- launch ----------------
extern "C" void kernel_launch(void* const* d_in, const int* in_sizes, int n_in,
                              void* d_out, int out_size) {
    const float* x = nullptr;
    const float* w[4] = {nullptr,nullptr,nullptr,nullptr};
    const float* pcm[4] = {nullptr,nullptr,nullptr,nullptr};
    const float* Wout = nullptr;
    for (int i = 0; i < n_in; i++) {
        switch (in_sizes[i]) {
            case 131072: x = (const float*)d_in[i]; break;
            case 2080:  w[0] = (const float*)d_in[i]; break;
            case 4120:  w[1] = (const float*)d_in[i]; break;
            case 6160:  w[2] = (const float*)d_in[i]; break;
            case 10240: w[3] = (const float*)d_in[i]; break;
            case 3688:  pcm[0] = (const float*)d_in[i]; break;
            case 3280:  pcm[1] = (const float*)d_in[i]; break;
            case 2872:  pcm[2] = (const float*)d_in[i]; break;
            case 2056:  pcm[3] = (const float*)d_in[i]; break;
            case 1600:  Wout = (const float*)d_in[i]; break;
            default: break;
        }
    }
    float* out = (float*)d_out;

    cudaFuncSetAttribute(k_main, cudaFuncAttributeMaxDynamicSharedMemorySize, SM_BYTES);

    k_main<<<NBLK, 256, SM_BYTES>>>(x, w[0], w[1], w[2], w[3],
                                    pcm[0], pcm[1], pcm[2], pcm[3]);
    k_final<<<NB + 1, 512>>>(out, Wout, w[0], w[1], w[2], w[3]);
    (void)out_size;
}